// round 3
// baseline (speedup 1.0000x reference)
#include <cuda_runtime.h>

#define H_HEADS 4
#define HIDD 256
#define B_SZ 16
#define U_SZ 64
#define T_SZ 128
#define E_DIM 128

// ---------------- scratch (device globals; no allocation allowed) ----------------
__device__ float g_u1[1024 * 128];
__device__ float g_u2[1024 * 128];
__device__ float g_uq[1024 * 256];
__device__ float g_t1[2048 * 128];
__device__ float g_t2[2048 * 128];
__device__ float g_kh[2048 * 256];
__device__ float g_Wq[128 * 256];
__device__ float g_Wk[128 * 256];
__device__ float g_bq[256];
__device__ float g_bk[256];
__device__ float g_hq[4 * 256];

// ---------------- prep: folded biases + per-head query projection ----------------
// blk0: bq[d]  = ub2 @ fw1[:128, d]
// blk1: bk[d]  = tb2 @ fw1[128:, d] + fb1[d]
// blk2..5: hq[h][d] = head_q[h] @ fw1[:128, d]
__global__ void prep_vec(const float* __restrict__ ub2, const float* __restrict__ tb2,
                         const float* __restrict__ fb1, const float* __restrict__ head_q,
                         const float* __restrict__ fw1)
{
    int d = threadIdx.x;  // 0..255
    int blk = blockIdx.x;
    if (blk == 0) {
        float s = 0.f;
        for (int e = 0; e < 128; e++) s += ub2[e] * fw1[e * HIDD + d];
        g_bq[d] = s;
    } else if (blk == 1) {
        float s = 0.f;
        for (int e = 0; e < 128; e++) s += tb2[e] * fw1[(128 + e) * HIDD + d];
        g_bk[d] = s + fb1[d];
    } else {
        int h = blk - 2;
        float s = 0.f;
        for (int e = 0; e < 128; e++) s += head_q[h * E_DIM + e] * fw1[e * HIDD + d];
        g_hq[h * HIDD + d] = s;
    }
}

// ---------------- generic 64x64 tiled fp32 GEMM, row-major, optional bias/relu ----------------
// C[M,N] = op(A[M,K] @ B[K,N] + bias)   requires M%64==0, N%64==0, K%16==0
template <bool RELU>
__global__ __launch_bounds__(256) void gemm64(const float* __restrict__ A,
                                              const float* __restrict__ B,
                                              const float* __restrict__ bias,
                                              float* __restrict__ C,
                                              int M, int N, int K)
{
    const int BK = 16;
    __shared__ float As[BK][64 + 1];
    __shared__ float Bs[BK][64];

    int tid = threadIdx.x;
    int bm = blockIdx.y * 64, bn = blockIdx.x * 64;
    int tm = (tid / 16) * 4, tn = (tid % 16) * 4;
    int arow = tid / 4, ak = (tid % 4) * 4;
    int brow = tid / 16, bcol = (tid % 16) * 4;

    float acc[4][4] = {};

    for (int k0 = 0; k0 < K; k0 += BK) {
        float4 av = *(const float4*)&A[(bm + arow) * K + k0 + ak];
        As[ak + 0][arow] = av.x;
        As[ak + 1][arow] = av.y;
        As[ak + 2][arow] = av.z;
        As[ak + 3][arow] = av.w;
        *(float4*)&Bs[brow][bcol] = *(const float4*)&B[(k0 + brow) * N + bn + bcol];
        __syncthreads();
#pragma unroll
        for (int k = 0; k < BK; k++) {
            float a0 = As[k][tm + 0], a1 = As[k][tm + 1], a2 = As[k][tm + 2], a3 = As[k][tm + 3];
            float4 bv = *(const float4*)&Bs[k][tn];
            acc[0][0] += a0 * bv.x; acc[0][1] += a0 * bv.y; acc[0][2] += a0 * bv.z; acc[0][3] += a0 * bv.w;
            acc[1][0] += a1 * bv.x; acc[1][1] += a1 * bv.y; acc[1][2] += a1 * bv.z; acc[1][3] += a1 * bv.w;
            acc[2][0] += a2 * bv.x; acc[2][1] += a2 * bv.y; acc[2][2] += a2 * bv.z; acc[2][3] += a2 * bv.w;
            acc[3][0] += a3 * bv.x; acc[3][1] += a3 * bv.y; acc[3][2] += a3 * bv.z; acc[3][3] += a3 * bv.w;
        }
        __syncthreads();
    }

    float b0 = 0.f, b1 = 0.f, b2 = 0.f, b3 = 0.f;
    if (bias) {
        b0 = bias[bn + tn + 0];
        b1 = bias[bn + tn + 1];
        b2 = bias[bn + tn + 2];
        b3 = bias[bn + tn + 3];
    }
#pragma unroll
    for (int i = 0; i < 4; i++) {
        float4 o;
        o.x = acc[i][0] + b0;
        o.y = acc[i][1] + b1;
        o.z = acc[i][2] + b2;
        o.w = acc[i][3] + b3;
        if (RELU) {
            o.x = fmaxf(o.x, 0.f); o.y = fmaxf(o.y, 0.f);
            o.z = fmaxf(o.z, 0.f); o.w = fmaxf(o.w, 0.f);
        }
        *(float4*)&C[(bm + tm + i) * N + bn + tn] = o;
    }
}

// ---------------- final: logits[b,h,u,t] = fb2 + sum_d relu(uq[b,u,d]+hq[h,d]+kh[b,t,d])*fw2[d] ----
// grid: (4 u-tiles, H, B), 256 threads. Each thread: 2 u x 4 t outputs.
__global__ __launch_bounds__(256) void final_kernel(const float* __restrict__ uq,
                                                    const float* __restrict__ kh,
                                                    const float* __restrict__ fw2,
                                                    const float* __restrict__ fb2,
                                                    float* __restrict__ out)
{
    const int DC = 64;
    __shared__ float ks[T_SZ][DC + 1];  // stride 65 -> conflict-free reads at t = lane + 32j
    __shared__ float qs[16][DC];
    __shared__ float ws[DC];

    int b = blockIdx.z, h = blockIdx.y, ut = blockIdx.x;
    int tid = threadIdx.x;
    int lane = tid & 31, wrp = tid >> 5;
    int ul0 = wrp * 2, ul1 = ul0 + 1;  // local u within 16-tile

    const float* hq = g_hq + h * HIDD;
    float acc[2][4] = {};

    for (int dc = 0; dc < HIDD; dc += DC) {
        // ---- load kh tile [128][64] ----
        {
            int d4 = tid & 15, tt = tid >> 4;
#pragma unroll
            for (int i = 0; i < 8; i++) {
                int t = tt + i * 16;
                float4 v = *(const float4*)&kh[(b * T_SZ + t) * HIDD + dc + d4 * 4];
                ks[t][d4 * 4 + 0] = v.x;
                ks[t][d4 * 4 + 1] = v.y;
                ks[t][d4 * 4 + 2] = v.z;
                ks[t][d4 * 4 + 3] = v.w;
            }
        }
        // ---- load q tile [16][64] = uq + hq ----
        {
            int uu = tid >> 4, d4 = tid & 15;
            float4 v = *(const float4*)&uq[(b * U_SZ + ut * 16 + uu) * HIDD + dc + d4 * 4];
            float4 hv = *(const float4*)&hq[dc + d4 * 4];
            qs[uu][d4 * 4 + 0] = v.x + hv.x;
            qs[uu][d4 * 4 + 1] = v.y + hv.y;
            qs[uu][d4 * 4 + 2] = v.z + hv.z;
            qs[uu][d4 * 4 + 3] = v.w + hv.w;
        }
        if (tid < DC) ws[tid] = fw2[dc + tid];
        __syncthreads();

#pragma unroll 8
        for (int d = 0; d < DC; d++) {
            float w = ws[d];
            float q0 = qs[ul0][d];
            float q1 = qs[ul1][d];
#pragma unroll
            for (int j = 0; j < 4; j++) {
                float kk = ks[lane + j * 32][d];
                acc[0][j] += fmaxf(q0 + kk, 0.f) * w;
                acc[1][j] += fmaxf(q1 + kk, 0.f) * w;
            }
        }
        __syncthreads();
    }

    float bias = fb2[0];
#pragma unroll
    for (int i = 0; i < 2; i++) {
        int u = ut * 16 + ul0 + i;
#pragma unroll
        for (int j = 0; j < 4; j++) {
            int t = lane + j * 32;
            out[(((b * H_HEADS) + h) * U_SZ + u) * T_SZ + t] = acc[i][j] + bias;
        }
    }
}

// ---------------- launch ----------------
extern "C" void kernel_launch(void* const* d_in, const int* in_sizes, int n_in,
                              void* d_out, int out_size)
{
    const float* uav    = (const float*)d_in[0];
    const float* task   = (const float*)d_in[1];
    const float* uw0    = (const float*)d_in[2];
    const float* ub0    = (const float*)d_in[3];
    const float* uw1    = (const float*)d_in[4];
    const float* ub1    = (const float*)d_in[5];
    const float* uw2    = (const float*)d_in[6];
    const float* ub2    = (const float*)d_in[7];
    const float* tw0    = (const float*)d_in[8];
    const float* tb0    = (const float*)d_in[9];
    const float* tw1    = (const float*)d_in[10];
    const float* tb1    = (const float*)d_in[11];
    const float* tw2    = (const float*)d_in[12];
    const float* tb2    = (const float*)d_in[13];
    const float* head_q = (const float*)d_in[14];
    const float* fw1    = (const float*)d_in[15];
    const float* fb1    = (const float*)d_in[16];
    const float* fw2    = (const float*)d_in[17];
    const float* fb2    = (const float*)d_in[18];
    float* out = (float*)d_out;

    float *p_u1, *p_u2, *p_uq, *p_t1, *p_t2, *p_kh, *p_Wq, *p_Wk, *p_bq, *p_bk;
    cudaGetSymbolAddress((void**)&p_u1, g_u1);
    cudaGetSymbolAddress((void**)&p_u2, g_u2);
    cudaGetSymbolAddress((void**)&p_uq, g_uq);
    cudaGetSymbolAddress((void**)&p_t1, g_t1);
    cudaGetSymbolAddress((void**)&p_t2, g_t2);
    cudaGetSymbolAddress((void**)&p_kh, g_kh);
    cudaGetSymbolAddress((void**)&p_Wq, g_Wq);
    cudaGetSymbolAddress((void**)&p_Wk, g_Wk);
    cudaGetSymbolAddress((void**)&p_bq, g_bq);
    cudaGetSymbolAddress((void**)&p_bk, g_bk);

    dim3 thr(256);

    // folded biases + head-query projection
    prep_vec<<<6, 256>>>(ub2, tb2, fb1, head_q, fw1);

    // folded projection weights: Wq' = uw2 @ fw1[:128], Wk' = tw2 @ fw1[128:]
    gemm64<false><<<dim3(4, 2), thr>>>(uw2, fw1,             nullptr, p_Wq, 128, 256, 128);
    gemm64<false><<<dim3(4, 2), thr>>>(tw2, fw1 + 128 * 256, nullptr, p_Wk, 128, 256, 128);

    // UAV path: (1024,32) -> relu(128) -> relu(128) -> uq(256)
    gemm64<true ><<<dim3(2, 16), thr>>>(uav,  uw0, ub0,  p_u1, 1024, 128, 32);
    gemm64<true ><<<dim3(2, 16), thr>>>(p_u1, uw1, ub1,  p_u2, 1024, 128, 128);
    gemm64<false><<<dim3(4, 16), thr>>>(p_u2, p_Wq, p_bq, p_uq, 1024, 256, 128);

    // Task path: (2048,32) -> relu(128) -> relu(128) -> kh(256)  (bias includes fb1)
    gemm64<true ><<<dim3(2, 32), thr>>>(task, tw0, tb0,  p_t1, 2048, 128, 32);
    gemm64<true ><<<dim3(2, 32), thr>>>(p_t1, tw1, tb1,  p_t2, 2048, 128, 128);
    gemm64<false><<<dim3(4, 32), thr>>>(p_t2, p_Wk, p_bk, p_kh, 2048, 256, 128);

    // fused relu-reduce
    final_kernel<<<dim3(4, H_HEADS, B_SZ), 256>>>(p_uq, p_kh, fw2, fb2, out);
}